// round 10
// baseline (speedup 1.0000x reference)
#include <cuda_runtime.h>
#include <cuda_bf16.h>
#include <cstdint>

#define N_BANDS    128
#define RESO       64
#define N_FRAMES   128
#define N_SAMPLES  32768
#define BATCH      16
#define N_ROWS     (BATCH * N_BANDS)

typedef unsigned long long u64;

// Dup'd frames: g_framesd[f*2048 + c*16 + b] = (v, v),  v = frames[b,c,f]
__device__ __align__(16) u64 g_framesd[N_FRAMES * N_ROWS];

__device__ __forceinline__ u64 fma2(u64 a, u64 b, u64 c) {
    u64 d;
    asm("fma.rn.f32x2 %0, %1, %2, %3;" : "=l"(d) : "l"(a), "l"(b), "l"(c));
    return d;
}
__device__ __forceinline__ u64 add2(u64 a, u64 b) {
    u64 d;
    asm("add.rn.f32x2 %0, %1, %2;" : "=l"(d) : "l"(a), "l"(b));
    return d;
}
__device__ __forceinline__ float u64lo(u64 v) {
    return __uint_as_float((unsigned int)(v & 0xFFFFFFFFull));
}
__device__ __forceinline__ float u64hi(u64 v) {
    return __uint_as_float((unsigned int)(v >> 32));
}

// ---------------------------------------------------------------------------
// Kernel 1: 128 blocks (block = band c) x 256 threads.
// softmax + matmul (f32x2 over r-pairs); writes dup'd u64 table directly.
// ---------------------------------------------------------------------------
__global__ __launch_bounds__(256)
void frames_kernel(const float* __restrict__ x,
                   const float* __restrict__ reso) {
    __shared__ float resT[N_FRAMES * 66];   // [f][r] padded stride 66
    __shared__ float pool2[2080];           // xs | ps

    float* xs = pool2;                 // [b*64 + r]
    float* ps = pool2 + 1024;          // [b*66 + r]

    const int tid = threadIdx.x;
    const int c = blockIdx.x;

    for (int idx = tid; idx < RESO * N_FRAMES; idx += 256) {
        const int r = idx >> 7;
        const int f = idx & 127;
        resT[f * 66 + r] = reso[idx];
    }
    for (int idx = tid; idx < 16 * RESO; idx += 256) {
        const int b = idx >> 6;
        const int r = idx & 63;
        xs[idx] = x[(b * 128 + c) * RESO + r];
    }
    __syncthreads();

    {
        const int w = tid >> 5;
        const int lane = tid & 31;
        #pragma unroll
        for (int rr = 0; rr < 2; ++rr) {
            const int row = w * 2 + rr;
            float v0 = xs[row * 64 + lane];
            float v1 = xs[row * 64 + lane + 32];
            float m = fmaxf(v0, v1);
            #pragma unroll
            for (int off = 16; off > 0; off >>= 1)
                m = fmaxf(m, __shfl_xor_sync(0xFFFFFFFFu, m, off));
            float e0 = __expf(v0 - m);
            float e1 = __expf(v1 - m);
            float s = e0 + e1;
            #pragma unroll
            for (int off = 16; off > 0; off >>= 1)
                s += __shfl_xor_sync(0xFFFFFFFFu, s, off);
            float inv = 1.0f / s;
            ps[row * 66 + lane]      = e0 * inv;
            ps[row * 66 + lane + 32] = e1 * inv;
        }
    }
    __syncthreads();

    {
        const int b  = tid & 15;
        const int f0 = tid >> 4;
        u64 acc2[8];
        #pragma unroll
        for (int i = 0; i < 8; ++i) acc2[i] = 0ull;

        #pragma unroll 4
        for (int rr = 0; rr < RESO / 2; ++rr) {
            const u64 psp =
                *reinterpret_cast<const u64*>(&ps[b * 66 + 2 * rr]);
            #pragma unroll
            for (int i = 0; i < 8; ++i) {
                const u64 rp = *reinterpret_cast<const u64*>(
                    &resT[(f0 + 16 * i) * 66 + 2 * rr]);
                acc2[i] = fma2(rp, psp, acc2[i]);
            }
        }
        #pragma unroll
        for (int i = 0; i < 8; ++i) {
            const float v = u64lo(acc2[i]) + u64hi(acc2[i]);
            const unsigned int vi = __float_as_uint(v);
            g_framesd[(f0 + 16 * i) * N_ROWS + c * 16 + b] =
                ((u64)vi << 32) | vi;
        }
    }
}

// ---------------------------------------------------------------------------
// Kernel 2: 512 blocks x 256 threads, 4 blocks/SM (smem 48KB).
// Block n = samples [64n, 64n+64); frame pair uniform: i0=(n<2)?0:(n-2)>>2.
// f32x2 lanes = adjacent samples; ih-split: warps 0-3 F0-dot, warps 4-7 F1.
// Thread (sg=tid&7: 8 samples, bq=(tid>>3)&3: 4 batches, ih, bs=tid>>6: 1/4
// of bands): per band 2 LDS.128 fb + 2 LDS.128 Fdup + 16 fma2  (ratio 1.25).
// 16 u64 accs. Epilogue: reduce over bs + combine ih halves via smem scratch
// (reuses F region), thread-local interp, one STG.128 per thread.
// ---------------------------------------------------------------------------
__global__ __launch_bounds__(256, 4)
void mix_kernel(const float* __restrict__ fb,
                float* __restrict__ out) {
    __shared__ __align__(16) u64   Fpool[2 * N_ROWS];   // 32 KB: F0 | F1
    __shared__ __align__(16) float fbbuf[2 * 2048];     // 16 KB ring (8KB ea)

    const int tid = threadIdx.x;
    const int n = blockIdx.x;
    const int s_base = n * 64;

    const int i0 = (n < 2) ? 0 : ((n - 2) >> 2);
    const int i1 = (i0 + 1 < N_FRAMES) ? i0 + 1 : N_FRAMES - 1;

    const unsigned int fb_s0 = (unsigned int)__cvta_generic_to_shared(&fbbuf[0]);
    const unsigned int Fp_s0 = (unsigned int)__cvta_generic_to_shared(&Fpool[0]);

    // fb chunk = 32 bands x 64 samples = 8 KB; 2 x 16B per thread.
#define STAGE_FB(CHUNK, BUF)                                                  \
    {                                                                         \
        _Pragma("unroll")                                                     \
        for (int i = 0; i < 2; ++i) {                                         \
            const int o = (i * 256 + tid) * 16;                               \
            const int band = o >> 8;                                          \
            const int within = o & 255;                                       \
            const float* g = fb + ((CHUNK) * 32 + band) * N_SAMPLES           \
                               + s_base + (within >> 2);                      \
            asm volatile("cp.async.cg.shared.global [%0], [%1], 16;\n"        \
                         :: "r"(fb_s0 + (BUF) * 8192 + o), "l"(g));           \
        }                                                                     \
        asm volatile("cp.async.commit_group;\n");                             \
    }

    // Group 0: F0 + F1 dup tables (32KB) + fb chunk 0.  Group 1: chunk 1.
    {
        const char* g0 = (const char*)(g_framesd + i0 * N_ROWS);
        const char* g1 = (const char*)(g_framesd + i1 * N_ROWS);
        #pragma unroll
        for (int i = 0; i < 4; ++i) {
            const int o = (i * 256 + tid) * 16;
            asm volatile("cp.async.cg.shared.global [%0], [%1], 16;\n"
                         :: "r"(Fp_s0 + o), "l"(g0 + o));
            asm volatile("cp.async.cg.shared.global [%0], [%1], 16;\n"
                         :: "r"(Fp_s0 + 16384 + o), "l"(g1 + o));
        }
        #pragma unroll
        for (int i = 0; i < 2; ++i) {
            const int o = (i * 256 + tid) * 16;
            const int band = o >> 8;
            const int within = o & 255;
            const float* g = fb + band * N_SAMPLES + s_base + (within >> 2);
            asm volatile("cp.async.cg.shared.global [%0], [%1], 16;\n"
                         :: "r"(fb_s0 + o), "l"(g));
        }
        asm volatile("cp.async.commit_group;\n");
    }
    STAGE_FB(1, 1);

    const int sg = tid & 7;              // 8-sample group (samples sg*8..+7)
    const int bq = (tid >> 3) & 3;       // batch quad (batches 4bq..4bq+3)
    const int ih = (tid >> 5) & 1;       // 0: F0 dot, 1: F1 dot
    const int bs = tid >> 6;             // band quarter within chunk
    const u64* __restrict__ Fd = Fpool + ih * N_ROWS;   // warp-uniform

    u64 acc[16];   // acc[jb*4+q]: batch 4bq+jb, sample pair q (s=sg*8+2q,+1)
    #pragma unroll
    for (int p = 0; p < 16; ++p) acc[p] = 0ull;

#define PROC(BUF, CH)                                                         \
    {                                                                         \
        _Pragma("unroll")                                                     \
        for (int cl = 0; cl < 8; ++cl) {                                      \
            const int cb = bs * 8 + cl;                                       \
            const int c  = (CH) * 32 + cb;                                    \
            const ulonglong2 f01 = *reinterpret_cast<const ulonglong2*>(      \
                &fbbuf[(BUF) * 2048 + cb * 64 + sg * 8]);                     \
            const ulonglong2 f23 = *reinterpret_cast<const ulonglong2*>(      \
                &fbbuf[(BUF) * 2048 + cb * 64 + sg * 8 + 4]);                 \
            const u64* Fr = Fd + c * 16 + bq * 4;                             \
            const ulonglong2 va = *reinterpret_cast<const ulonglong2*>(Fr);   \
            const ulonglong2 vb = *reinterpret_cast<const ulonglong2*>(Fr+2); \
            acc[0]  = fma2(va.x, f01.x, acc[0]);                              \
            acc[1]  = fma2(va.x, f01.y, acc[1]);                              \
            acc[2]  = fma2(va.x, f23.x, acc[2]);                              \
            acc[3]  = fma2(va.x, f23.y, acc[3]);                              \
            acc[4]  = fma2(va.y, f01.x, acc[4]);                              \
            acc[5]  = fma2(va.y, f01.y, acc[5]);                              \
            acc[6]  = fma2(va.y, f23.x, acc[6]);                              \
            acc[7]  = fma2(va.y, f23.y, acc[7]);                              \
            acc[8]  = fma2(vb.x, f01.x, acc[8]);                              \
            acc[9]  = fma2(vb.x, f01.y, acc[9]);                              \
            acc[10] = fma2(vb.x, f23.x, acc[10]);                             \
            acc[11] = fma2(vb.x, f23.y, acc[11]);                             \
            acc[12] = fma2(vb.y, f01.x, acc[12]);                             \
            acc[13] = fma2(vb.y, f01.y, acc[13]);                             \
            acc[14] = fma2(vb.y, f23.x, acc[14]);                             \
            acc[15] = fma2(vb.y, f23.y, acc[15]);                             \
        }                                                                     \
    }

#define WAITG(N) asm volatile("cp.async.wait_group %0;\n" :: "n"(N) : "memory")

    WAITG(1); __syncthreads(); PROC(0, 0);
    __syncthreads(); STAGE_FB(2, 0);
    WAITG(1); __syncthreads(); PROC(1, 1);
    __syncthreads(); STAGE_FB(3, 1);
    WAITG(1); __syncthreads(); PROC(0, 2);
    WAITG(0); __syncthreads(); PROC(1, 3);

#undef STAGE_FB
#undef PROC
#undef WAITG

    // --- Epilogue: scratch = Fpool region (32KB = 256 threads x 16 u64) ---
    __syncthreads();   // all reads of Fpool/fbbuf done
    u64* S = Fpool;    // S[tid*16 + p]
    #pragma unroll
    for (int p = 0; p < 16; ++p) S[tid * 16 + p] = acc[p];
    __syncthreads();

    {
        const int b = tid >> 4;          // batch 0..15
        const int k = tid & 15;          // 4-sample group: samples 4k..4k+3
        const int e_bq = b >> 2;
        const int e_jb = b & 3;
        const int e_sg = k >> 1;
        const int q0   = (k & 1) * 2;
        const int s0 = s_base + k * 4;

        float w[4];
        #pragma unroll
        for (int j = 0; j < 4; ++j) {
            float pos = (float)(s0 + j) * (1.0f / 256.0f)
                        + (0.5f / 256.0f - 0.5f);
            pos = fminf(fmaxf(pos, 0.0f), 127.0f);
            w[j] = pos - floorf(pos);
        }

        float4 o;
        float* ov = &o.x;
        #pragma unroll
        for (int pp = 0; pp < 2; ++pp) {
            const int p = q0 + pp;
            const int pay = e_jb * 4 + p;
            u64 A0 = 0ull, A1 = 0ull;
            #pragma unroll
            for (int bsx = 0; bsx < 4; ++bsx) {
                const int t0 = e_sg + 8 * e_bq + 0  + 64 * bsx;
                const int t1 = e_sg + 8 * e_bq + 32 + 64 * bsx;
                A0 = add2(A0, S[t0 * 16 + pay]);
                A1 = add2(A1, S[t1 * 16 + pay]);
            }
            const float a0l = u64lo(A0), a0h = u64hi(A0);
            const float a1l = u64lo(A1), a1h = u64hi(A1);
            ov[2 * pp]     = fmaf(w[2 * pp],     a1l - a0l, a0l) * (1.0f / 128.0f);
            ov[2 * pp + 1] = fmaf(w[2 * pp + 1], a1h - a0h, a0h) * (1.0f / 128.0f);
        }
        *reinterpret_cast<float4*>(out + b * N_SAMPLES + s0) = o;
    }
}

// ---------------------------------------------------------------------------
extern "C" void kernel_launch(void* const* d_in, const int* in_sizes, int n_in,
                              void* d_out, int out_size) {
    const float* x = nullptr;      // (16,128,64)    = 131072
    const float* reso = nullptr;   // (64,128)       = 8192
    const float* fb = nullptr;     // (1,128,32768)  = 4194304
    for (int i = 0; i < n_in; ++i) {
        if (in_sizes[i] == BATCH * N_BANDS * RESO)      x = (const float*)d_in[i];
        else if (in_sizes[i] == RESO * N_FRAMES)        reso = (const float*)d_in[i];
        else if (in_sizes[i] == N_BANDS * N_SAMPLES)    fb = (const float*)d_in[i];
    }
    float* out = (float*)d_out;

    frames_kernel<<<N_BANDS, 256>>>(x, reso);
    mix_kernel<<<N_SAMPLES / 64, 256>>>(fb, out);
}

// round 11
// speedup vs baseline: 1.2667x; 1.2667x over previous
#include <cuda_runtime.h>
#include <cuda_bf16.h>
#include <cstdint>

#define N_BANDS    128
#define RESO       64
#define N_FRAMES   128
#define N_SAMPLES  32768
#define BATCH      16
#define N_ROWS     (BATCH * N_BANDS)

typedef unsigned long long u64;

// Dup'd frames: g_framesd[f*2048 + c*16 + b] = (v, v),  v = frames[b,c,f]
__device__ __align__(16) u64 g_framesd[N_FRAMES * N_ROWS];

__device__ __forceinline__ u64 fma2(u64 a, u64 b, u64 c) {
    u64 d;
    asm("fma.rn.f32x2 %0, %1, %2, %3;" : "=l"(d) : "l"(a), "l"(b), "l"(c));
    return d;
}
__device__ __forceinline__ u64 add2(u64 a, u64 b) {
    u64 d;
    asm("add.rn.f32x2 %0, %1, %2;" : "=l"(d) : "l"(a), "l"(b));
    return d;
}
__device__ __forceinline__ float u64lo(u64 v) {
    return __uint_as_float((unsigned int)(v & 0xFFFFFFFFull));
}
__device__ __forceinline__ float u64hi(u64 v) {
    return __uint_as_float((unsigned int)(v >> 32));
}

// ---------------------------------------------------------------------------
// Kernel 1: 128 blocks (block = band c) x 256 threads.
// softmax + matmul (f32x2 over r-pairs); writes dup'd u64 table directly.
// ---------------------------------------------------------------------------
__global__ __launch_bounds__(256)
void frames_kernel(const float* __restrict__ x,
                   const float* __restrict__ reso) {
    __shared__ float resT[N_FRAMES * 66];   // [f][r] padded stride 66
    __shared__ float pool2[2080];           // xs | ps

    float* xs = pool2;                 // [b*64 + r]
    float* ps = pool2 + 1024;          // [b*66 + r]

    const int tid = threadIdx.x;
    const int c = blockIdx.x;

    for (int idx = tid; idx < RESO * N_FRAMES; idx += 256) {
        const int r = idx >> 7;
        const int f = idx & 127;
        resT[f * 66 + r] = reso[idx];
    }
    for (int idx = tid; idx < 16 * RESO; idx += 256) {
        const int b = idx >> 6;
        const int r = idx & 63;
        xs[idx] = x[(b * 128 + c) * RESO + r];
    }
    __syncthreads();

    {
        const int w = tid >> 5;
        const int lane = tid & 31;
        #pragma unroll
        for (int rr = 0; rr < 2; ++rr) {
            const int row = w * 2 + rr;
            float v0 = xs[row * 64 + lane];
            float v1 = xs[row * 64 + lane + 32];
            float m = fmaxf(v0, v1);
            #pragma unroll
            for (int off = 16; off > 0; off >>= 1)
                m = fmaxf(m, __shfl_xor_sync(0xFFFFFFFFu, m, off));
            float e0 = __expf(v0 - m);
            float e1 = __expf(v1 - m);
            float s = e0 + e1;
            #pragma unroll
            for (int off = 16; off > 0; off >>= 1)
                s += __shfl_xor_sync(0xFFFFFFFFu, s, off);
            float inv = 1.0f / s;
            ps[row * 66 + lane]      = e0 * inv;
            ps[row * 66 + lane + 32] = e1 * inv;
        }
    }
    __syncthreads();

    {
        const int b  = tid & 15;
        const int f0 = tid >> 4;
        u64 acc2[8];
        #pragma unroll
        for (int i = 0; i < 8; ++i) acc2[i] = 0ull;

        #pragma unroll 4
        for (int rr = 0; rr < RESO / 2; ++rr) {
            const u64 psp =
                *reinterpret_cast<const u64*>(&ps[b * 66 + 2 * rr]);
            #pragma unroll
            for (int i = 0; i < 8; ++i) {
                const u64 rp = *reinterpret_cast<const u64*>(
                    &resT[(f0 + 16 * i) * 66 + 2 * rr]);
                acc2[i] = fma2(rp, psp, acc2[i]);
            }
        }
        #pragma unroll
        for (int i = 0; i < 8; ++i) {
            const float v = u64lo(acc2[i]) + u64hi(acc2[i]);
            const unsigned int vi = __float_as_uint(v);
            g_framesd[(f0 + 16 * i) * N_ROWS + c * 16 + b] =
                ((u64)vi << 32) | vi;
        }
    }
}

// ---------------------------------------------------------------------------
// Kernel 2: 512 blocks x 256 threads, 4 blocks/SM (smem 48KB).
// Block n = samples [64n, 64n+64); frame pair uniform: i0=(n<2)?0:(n-2)>>2.
// f32x2 lanes = adjacent samples; ih-split: F0-dot / F1-dot warp halves.
// Thread (sg=tid&7: 8 samples, bq=(tid>>3)&3: 4 batches, ih=(tid>>5)&1,
// bs=tid>>6: band quarter): per band 2 LDS.128 fb + 2 LDS.128 Fdup + 16 fma2.
// Epilogue scratch is PAYLOAD-MAJOR (S[p*256+tid]) -> conflict-free stores.
// ---------------------------------------------------------------------------
__global__ __launch_bounds__(256, 4)
void mix_kernel(const float* __restrict__ fb,
                float* __restrict__ out) {
    __shared__ __align__(16) u64   Fpool[2 * N_ROWS];   // 32 KB: F0 | F1
    __shared__ __align__(16) float fbbuf[2 * 2048];     // 16 KB ring (8KB ea)

    const int tid = threadIdx.x;
    const int n = blockIdx.x;
    const int s_base = n * 64;

    const int i0 = (n < 2) ? 0 : ((n - 2) >> 2);
    const int i1 = (i0 + 1 < N_FRAMES) ? i0 + 1 : N_FRAMES - 1;

    const unsigned int fb_s0 = (unsigned int)__cvta_generic_to_shared(&fbbuf[0]);
    const unsigned int Fp_s0 = (unsigned int)__cvta_generic_to_shared(&Fpool[0]);

    // fb chunk = 32 bands x 64 samples = 8 KB; 2 x 16B per thread.
#define STAGE_FB(CHUNK, BUF)                                                  \
    {                                                                         \
        _Pragma("unroll")                                                     \
        for (int i = 0; i < 2; ++i) {                                         \
            const int o = (i * 256 + tid) * 16;                               \
            const int band = o >> 8;                                          \
            const int within = o & 255;                                       \
            const float* g = fb + ((CHUNK) * 32 + band) * N_SAMPLES           \
                               + s_base + (within >> 2);                      \
            asm volatile("cp.async.cg.shared.global [%0], [%1], 16;\n"        \
                         :: "r"(fb_s0 + (BUF) * 8192 + o), "l"(g));           \
        }                                                                     \
        asm volatile("cp.async.commit_group;\n");                             \
    }

    // Group 0: F0 + F1 dup tables (32KB) + fb chunk 0.  Group 1: chunk 1.
    {
        const char* g0 = (const char*)(g_framesd + i0 * N_ROWS);
        const char* g1 = (const char*)(g_framesd + i1 * N_ROWS);
        #pragma unroll
        for (int i = 0; i < 4; ++i) {
            const int o = (i * 256 + tid) * 16;
            asm volatile("cp.async.cg.shared.global [%0], [%1], 16;\n"
                         :: "r"(Fp_s0 + o), "l"(g0 + o));
            asm volatile("cp.async.cg.shared.global [%0], [%1], 16;\n"
                         :: "r"(Fp_s0 + 16384 + o), "l"(g1 + o));
        }
        #pragma unroll
        for (int i = 0; i < 2; ++i) {
            const int o = (i * 256 + tid) * 16;
            const int band = o >> 8;
            const int within = o & 255;
            const float* g = fb + band * N_SAMPLES + s_base + (within >> 2);
            asm volatile("cp.async.cg.shared.global [%0], [%1], 16;\n"
                         :: "r"(fb_s0 + o), "l"(g));
        }
        asm volatile("cp.async.commit_group;\n");
    }
    STAGE_FB(1, 1);

    const int sg = tid & 7;              // 8-sample group (samples sg*8..+7)
    const int bq = (tid >> 3) & 3;       // batch quad (batches 4bq..4bq+3)
    const int ih = (tid >> 5) & 1;       // 0: F0 dot, 1: F1 dot
    const int bs = tid >> 6;             // band quarter within chunk
    const u64* __restrict__ Fd = Fpool + ih * N_ROWS;   // warp-uniform

    u64 acc[16];   // acc[jb*4+q]: batch 4bq+jb, sample pair q (s=sg*8+2q,+1)
    #pragma unroll
    for (int p = 0; p < 16; ++p) acc[p] = 0ull;

#define PROC(BUF, CH)                                                         \
    {                                                                         \
        _Pragma("unroll")                                                     \
        for (int cl = 0; cl < 8; ++cl) {                                      \
            const int cb = bs * 8 + cl;                                       \
            const int c  = (CH) * 32 + cb;                                    \
            const ulonglong2 f01 = *reinterpret_cast<const ulonglong2*>(      \
                &fbbuf[(BUF) * 2048 + cb * 64 + sg * 8]);                     \
            const ulonglong2 f23 = *reinterpret_cast<const ulonglong2*>(      \
                &fbbuf[(BUF) * 2048 + cb * 64 + sg * 8 + 4]);                 \
            const u64* Fr = Fd + c * 16 + bq * 4;                             \
            const ulonglong2 va = *reinterpret_cast<const ulonglong2*>(Fr);   \
            const ulonglong2 vb = *reinterpret_cast<const ulonglong2*>(Fr+2); \
            acc[0]  = fma2(va.x, f01.x, acc[0]);                              \
            acc[1]  = fma2(va.x, f01.y, acc[1]);                              \
            acc[2]  = fma2(va.x, f23.x, acc[2]);                              \
            acc[3]  = fma2(va.x, f23.y, acc[3]);                              \
            acc[4]  = fma2(va.y, f01.x, acc[4]);                              \
            acc[5]  = fma2(va.y, f01.y, acc[5]);                              \
            acc[6]  = fma2(va.y, f23.x, acc[6]);                              \
            acc[7]  = fma2(va.y, f23.y, acc[7]);                              \
            acc[8]  = fma2(vb.x, f01.x, acc[8]);                              \
            acc[9]  = fma2(vb.x, f01.y, acc[9]);                              \
            acc[10] = fma2(vb.x, f23.x, acc[10]);                             \
            acc[11] = fma2(vb.x, f23.y, acc[11]);                             \
            acc[12] = fma2(vb.y, f01.x, acc[12]);                             \
            acc[13] = fma2(vb.y, f01.y, acc[13]);                             \
            acc[14] = fma2(vb.y, f23.x, acc[14]);                             \
            acc[15] = fma2(vb.y, f23.y, acc[15]);                             \
        }                                                                     \
    }

#define WAITG(N) asm volatile("cp.async.wait_group %0;\n" :: "n"(N) : "memory")

    WAITG(1); __syncthreads(); PROC(0, 0);
    __syncthreads(); STAGE_FB(2, 0);
    WAITG(1); __syncthreads(); PROC(1, 1);
    __syncthreads(); STAGE_FB(3, 1);
    WAITG(1); __syncthreads(); PROC(0, 2);
    WAITG(0); __syncthreads(); PROC(1, 3);

#undef STAGE_FB
#undef PROC
#undef WAITG

    // --- Epilogue: PAYLOAD-MAJOR scratch S[p*256 + tid] (conflict-free) ---
    __syncthreads();   // all reads of Fpool/fbbuf done
    u64* S = Fpool;    // 4096 u64 = 32 KB = 16 payloads x 256 threads
    #pragma unroll
    for (int p = 0; p < 16; ++p) S[p * 256 + tid] = acc[p];
    __syncthreads();

    {
        const int b = tid >> 4;          // batch 0..15
        const int k = tid & 15;          // 4-sample group: samples 4k..4k+3
        const int e_bq = b >> 2;
        const int e_jb = b & 3;
        const int e_sg = k >> 1;
        const int q0   = (k & 1) * 2;
        const int s0 = s_base + k * 4;

        float w[4];
        #pragma unroll
        for (int j = 0; j < 4; ++j) {
            float pos = (float)(s0 + j) * (1.0f / 256.0f)
                        + (0.5f / 256.0f - 0.5f);
            pos = fminf(fmaxf(pos, 0.0f), 127.0f);
            w[j] = pos - floorf(pos);
        }

        float4 o;
        float* ov = &o.x;
        #pragma unroll
        for (int pp = 0; pp < 2; ++pp) {
            const int pay = e_jb * 4 + q0 + pp;
            u64 A0 = 0ull, A1 = 0ull;
            #pragma unroll
            for (int bsx = 0; bsx < 4; ++bsx) {
                const int t0 = e_sg + 8 * e_bq + 0  + 64 * bsx;
                const int t1 = e_sg + 8 * e_bq + 32 + 64 * bsx;
                A0 = add2(A0, S[pay * 256 + t0]);
                A1 = add2(A1, S[pay * 256 + t1]);
            }
            const float a0l = u64lo(A0), a0h = u64hi(A0);
            const float a1l = u64lo(A1), a1h = u64hi(A1);
            ov[2 * pp]     = fmaf(w[2 * pp],     a1l - a0l, a0l) * (1.0f / 128.0f);
            ov[2 * pp + 1] = fmaf(w[2 * pp + 1], a1h - a0h, a0h) * (1.0f / 128.0f);
        }
        *reinterpret_cast<float4*>(out + b * N_SAMPLES + s0) = o;
    }
}

// ---------------------------------------------------------------------------
extern "C" void kernel_launch(void* const* d_in, const int* in_sizes, int n_in,
                              void* d_out, int out_size) {
    const float* x = nullptr;      // (16,128,64)    = 131072
    const float* reso = nullptr;   // (64,128)       = 8192
    const float* fb = nullptr;     // (1,128,32768)  = 4194304
    for (int i = 0; i < n_in; ++i) {
        if (in_sizes[i] == BATCH * N_BANDS * RESO)      x = (const float*)d_in[i];
        else if (in_sizes[i] == RESO * N_FRAMES)        reso = (const float*)d_in[i];
        else if (in_sizes[i] == N_BANDS * N_SAMPLES)    fb = (const float*)d_in[i];
    }
    float* out = (float*)d_out;

    frames_kernel<<<N_BANDS, 256>>>(x, reso);
    mix_kernel<<<N_SAMPLES / 64, 256>>>(fb, out);
}

// round 12
// speedup vs baseline: 1.5225x; 1.2020x over previous
#include <cuda_runtime.h>
#include <cuda_bf16.h>
#include <cstdint>

#define N_BANDS    128
#define RESO       64
#define N_FRAMES   128
#define N_SAMPLES  32768
#define BATCH      16
#define N_ROWS     (BATCH * N_BANDS)

typedef unsigned long long u64;

// Pair table: g_framep[i*2048 + c*16 + b] = (frames[b,c,i], frames[b,c,min(i+1,127)])
__device__ __align__(16) float2 g_framep[N_FRAMES * N_ROWS];

__device__ __forceinline__ u64 fma2(u64 a, u64 b, u64 c) {
    u64 d;
    asm("fma.rn.f32x2 %0, %1, %2, %3;" : "=l"(d) : "l"(a), "l"(b), "l"(c));
    return d;
}
__device__ __forceinline__ u64 add2(u64 a, u64 b) {
    u64 d;
    asm("add.rn.f32x2 %0, %1, %2;" : "=l"(d) : "l"(a), "l"(b));
    return d;
}
__device__ __forceinline__ u64 dup32(float x) {
    u64 r;
    unsigned int xi = __float_as_uint(x);
    asm("mov.b64 %0, {%1, %1};" : "=l"(r) : "r"(xi));
    return r;
}
__device__ __forceinline__ float u64lo(u64 v) {
    return __uint_as_float((unsigned int)(v & 0xFFFFFFFFull));
}
__device__ __forceinline__ float u64hi(u64 v) {
    return __uint_as_float((unsigned int)(v >> 32));
}

// ---------------------------------------------------------------------------
// Kernel 1: 128 blocks (block = band c) x 256 threads. (round-8 version)
// softmax + matmul (f32x2 over r-pairs), writes (f_i, f_{i+1}) pairs coalesced.
// ---------------------------------------------------------------------------
__global__ __launch_bounds__(256)
void frames_kernel(const float* __restrict__ x,
                   const float* __restrict__ reso) {
    __shared__ float resT[N_FRAMES * 66];   // [f][r] padded stride 66
    __shared__ float pool2[2080];           // xs | ps; fr aliases after sync

    float* xs = pool2;                 // [b*64 + r]
    float* ps = pool2 + 1024;          // [b*66 + r]
    float* fr = pool2;                 // [f*16 + b]

    const int tid = threadIdx.x;
    const int c = blockIdx.x;

    for (int idx = tid; idx < RESO * N_FRAMES; idx += 256) {
        const int r = idx >> 7;
        const int f = idx & 127;
        resT[f * 66 + r] = reso[idx];
    }
    for (int idx = tid; idx < 16 * RESO; idx += 256) {
        const int b = idx >> 6;
        const int r = idx & 63;
        xs[idx] = x[(b * 128 + c) * RESO + r];
    }
    __syncthreads();

    {
        const int w = tid >> 5;
        const int lane = tid & 31;
        #pragma unroll
        for (int rr = 0; rr < 2; ++rr) {
            const int row = w * 2 + rr;
            float v0 = xs[row * 64 + lane];
            float v1 = xs[row * 64 + lane + 32];
            float m = fmaxf(v0, v1);
            #pragma unroll
            for (int off = 16; off > 0; off >>= 1)
                m = fmaxf(m, __shfl_xor_sync(0xFFFFFFFFu, m, off));
            float e0 = __expf(v0 - m);
            float e1 = __expf(v1 - m);
            float s = e0 + e1;
            #pragma unroll
            for (int off = 16; off > 0; off >>= 1)
                s += __shfl_xor_sync(0xFFFFFFFFu, s, off);
            float inv = 1.0f / s;
            ps[row * 66 + lane]      = e0 * inv;
            ps[row * 66 + lane + 32] = e1 * inv;
        }
    }
    __syncthreads();

    float v[8];
    {
        const int b  = tid & 15;
        const int f0 = tid >> 4;
        u64 acc2[8];
        #pragma unroll
        for (int i = 0; i < 8; ++i) acc2[i] = 0ull;

        #pragma unroll 4
        for (int rr = 0; rr < RESO / 2; ++rr) {
            const u64 psp =
                *reinterpret_cast<const u64*>(&ps[b * 66 + 2 * rr]);
            #pragma unroll
            for (int i = 0; i < 8; ++i) {
                const u64 rp = *reinterpret_cast<const u64*>(
                    &resT[(f0 + 16 * i) * 66 + 2 * rr]);
                acc2[i] = fma2(rp, psp, acc2[i]);
            }
        }
        #pragma unroll
        for (int i = 0; i < 8; ++i) v[i] = u64lo(acc2[i]) + u64hi(acc2[i]);
    }
    __syncthreads();

    {
        const int b  = tid & 15;
        const int f0 = tid >> 4;
        #pragma unroll
        for (int i = 0; i < 8; ++i)
            fr[(f0 + 16 * i) * 16 + b] = v[i];
    }
    __syncthreads();

    {
        const int b  = tid & 15;
        const int f0 = tid >> 4;
        #pragma unroll
        for (int k = 0; k < 8; ++k) {
            const int p = f0 + 16 * k;
            const int pn = (p + 1 < N_FRAMES) ? p + 1 : N_FRAMES - 1;
            const float lo = fr[p * 16 + b];
            const float hi = fr[pn * 16 + b];
            g_framep[p * N_ROWS + c * 16 + b] = make_float2(lo, hi);
        }
    }
}

// ---------------------------------------------------------------------------
// Kernel 2: 512 blocks x 256 threads, 4 blocks/SM (smem 48KB).
// Block n = samples [64n, 64n+64); frame pair uniform: i0=(n<2)?0:(n-2)>>2.
// Round-8 hot loop (f32x2 lanes = (F0-dot, F1-dot)): per band
// 1 LDS.128 fb + 4 dup MOV + 1 LDS.128 FP + 8 fma2.
// NEW: all 4 fb chunks have dedicated buffers; ALL cp.async issued upfront
// (4 groups: FP+chunk0, chunk1, chunk2, chunk3); staggered waits, no buffer
// reuse, no post-PROC syncs. Payload-major epilogue scratch.
// ---------------------------------------------------------------------------
__global__ __launch_bounds__(256, 4)
void mix_kernel(const float* __restrict__ fb,
                float* __restrict__ out) {
    __shared__ __align__(16) float fbbuf[4 * 2048];   // 32 KB, 4 chunks
    __shared__ __align__(16) u64 FPs[N_ROWS];         // 16 KB pair table

    const int tid = threadIdx.x;
    const int n = blockIdx.x;
    const int s_base = n * 64;

    const int i0 = (n < 2) ? 0 : ((n - 2) >> 2);

    const unsigned int fb_s0 = (unsigned int)__cvta_generic_to_shared(&fbbuf[0]);
    const unsigned int FP_s0 = (unsigned int)__cvta_generic_to_shared(&FPs[0]);

    // fb chunk = 32 bands x 64 samples = 8 KB; 2 x 16B per thread.
#define STAGE_FB(CHUNK)                                                       \
    {                                                                         \
        _Pragma("unroll")                                                     \
        for (int i = 0; i < 2; ++i) {                                         \
            const int o = (i * 256 + tid) * 16;                               \
            const int band = o >> 8;                                          \
            const int within = o & 255;                                       \
            const float* g = fb + ((CHUNK) * 32 + band) * N_SAMPLES           \
                               + s_base + (within >> 2);                      \
            asm volatile("cp.async.cg.shared.global [%0], [%1], 16;\n"        \
                         :: "r"(fb_s0 + (CHUNK) * 8192 + o), "l"(g));         \
        }                                                                     \
        asm volatile("cp.async.commit_group;\n");                             \
    }

    // Group 0: FP pair table (16KB) + fb chunk 0.  Groups 1-3: chunks 1-3.
    {
        const char* gp = (const char*)(g_framep + i0 * N_ROWS);
        #pragma unroll
        for (int i = 0; i < 4; ++i) {
            const int o = (i * 256 + tid) * 16;
            asm volatile("cp.async.cg.shared.global [%0], [%1], 16;\n"
                         :: "r"(FP_s0 + o), "l"(gp + o));
        }
        #pragma unroll
        for (int i = 0; i < 2; ++i) {
            const int o = (i * 256 + tid) * 16;
            const int band = o >> 8;
            const int within = o & 255;
            const float* g = fb + band * N_SAMPLES + s_base + (within >> 2);
            asm volatile("cp.async.cg.shared.global [%0], [%1], 16;\n"
                         :: "r"(fb_s0 + o), "l"(g));
        }
        asm volatile("cp.async.commit_group;\n");
    }
    STAGE_FB(1);
    STAGE_FB(2);
    STAGE_FB(3);

    const int sg = tid & 15;             // 4-sample group
    const int bq = (tid >> 4) & 7;       // batch pair (batches 2bq, 2bq+1)
    const int bs = tid >> 7;             // band half (16 of each 32-chunk)

    u64 acc[8];   // acc[bp*4+j]: batch 2bq+bp, sample j; lanes (dot0, dot1)
    #pragma unroll
    for (int p = 0; p < 8; ++p) acc[p] = 0ull;

#define PROC(CH)                                                              \
    {                                                                         \
        _Pragma("unroll 4")                                                   \
        for (int cl = 0; cl < 16; ++cl) {                                     \
            const int cb = bs * 16 + cl;                                      \
            const int c  = (CH) * 32 + cb;                                    \
            const float4 fv = *reinterpret_cast<const float4*>(               \
                &fbbuf[(CH) * 2048 + cb * 64 + sg * 4]);                      \
            const u64 d0 = dup32(fv.x);                                       \
            const u64 d1 = dup32(fv.y);                                       \
            const u64 d2 = dup32(fv.z);                                       \
            const u64 d3 = dup32(fv.w);                                       \
            const ulonglong2 fp2 = *reinterpret_cast<const ulonglong2*>(      \
                &FPs[c * 16 + bq * 2]);                                       \
            acc[0] = fma2(fp2.x, d0, acc[0]);                                 \
            acc[1] = fma2(fp2.x, d1, acc[1]);                                 \
            acc[2] = fma2(fp2.x, d2, acc[2]);                                 \
            acc[3] = fma2(fp2.x, d3, acc[3]);                                 \
            acc[4] = fma2(fp2.y, d0, acc[4]);                                 \
            acc[5] = fma2(fp2.y, d1, acc[5]);                                 \
            acc[6] = fma2(fp2.y, d2, acc[6]);                                 \
            acc[7] = fma2(fp2.y, d3, acc[7]);                                 \
        }                                                                     \
    }

#define WAITG(N) asm volatile("cp.async.wait_group %0;\n" :: "n"(N) : "memory")

    WAITG(3); __syncthreads(); PROC(0);
    WAITG(2); __syncthreads(); PROC(1);
    WAITG(1); __syncthreads(); PROC(2);
    WAITG(0); __syncthreads(); PROC(3);

#undef STAGE_FB
#undef PROC
#undef WAITG

    // --- Epilogue: payload-major scratch (conflict-free both directions) ---
    __syncthreads();   // all reads of FPs/fbbuf done
    u64* S = reinterpret_cast<u64*>(&fbbuf[0]);   // 8 payloads x 128 = 8KB
    if (tid >= 128) {
        const int j = tid - 128;
        #pragma unroll
        for (int p = 0; p < 8; ++p) S[p * 128 + j] = acc[p];
    }
    __syncthreads();
    if (tid < 128) {
        const int s0 = s_base + sg * 4;
        float w[4];
        #pragma unroll
        for (int j = 0; j < 4; ++j) {
            float pos = (float)(s0 + j) * (1.0f / 256.0f)
                        + (0.5f / 256.0f - 0.5f);
            pos = fminf(fmaxf(pos, 0.0f), 127.0f);
            w[j] = pos - floorf(pos);
        }
        #pragma unroll
        for (int bp = 0; bp < 2; ++bp) {
            float4 o;
            float* ov = &o.x;
            #pragma unroll
            for (int j = 0; j < 4; ++j) {
                const u64 A = add2(acc[bp * 4 + j],
                                   S[(bp * 4 + j) * 128 + tid]);
                const float a0 = u64lo(A);
                const float a1 = u64hi(A);
                ov[j] = fmaf(w[j], a1 - a0, a0) * (1.0f / 128.0f);
            }
            *reinterpret_cast<float4*>(
                out + (bq * 2 + bp) * N_SAMPLES + s0) = o;
        }
    }
}

// ---------------------------------------------------------------------------
extern "C" void kernel_launch(void* const* d_in, const int* in_sizes, int n_in,
                              void* d_out, int out_size) {
    const float* x = nullptr;      // (16,128,64)    = 131072
    const float* reso = nullptr;   // (64,128)       = 8192
    const float* fb = nullptr;     // (1,128,32768)  = 4194304
    for (int i = 0; i < n_in; ++i) {
        if (in_sizes[i] == BATCH * N_BANDS * RESO)      x = (const float*)d_in[i];
        else if (in_sizes[i] == RESO * N_FRAMES)        reso = (const float*)d_in[i];
        else if (in_sizes[i] == N_BANDS * N_SAMPLES)    fb = (const float*)d_in[i];
    }
    float* out = (float*)d_out;

    frames_kernel<<<N_BANDS, 256>>>(x, reso);
    mix_kernel<<<N_SAMPLES / 64, 256>>>(fb, out);
}